// round 2
// baseline (speedup 1.0000x reference)
#include <cuda_runtime.h>
#include <math_constants.h>

// ---------------- problem constants ----------------
#define BATCH 4
#define HW    16384          // 128*128
#define THR   0.1f
#define TS    2048           // shared column tile == column chunk
#define RPT   8              // rows per thread in dist kernel
#define DBLK  256            // threads per dist block  -> 2048 rows/block
#define ROWCHUNK (DBLK*RPT)  // 2048
#define COLCHUNK 2048

// ---------------- device scratch (no allocs allowed) ----------------
__device__ float g_px[2][BATCH][HW];
__device__ float g_py[2][BATCH][HW];
__device__ float g_pn[2][BATCH][HW];
__device__ int   g_cnt[2][BATCH];
__device__ unsigned int g_minbuf[8][HW];   // [dir*4+b][row], orderable-uint encoded
__device__ float g_sum[8];

// ---------------- helpers ----------------
__device__ __forceinline__ unsigned fp_ord(float f) {
    unsigned u = __float_as_uint(f);
    return (u & 0x80000000u) ? ~u : (u | 0x80000000u);
}
__device__ __forceinline__ float fp_unord(unsigned u) {
    u = (u & 0x80000000u) ? (u & 0x7fffffffu) : ~u;
    return __uint_as_float(u);
}
__device__ __forceinline__ unsigned long long pack2(float lo, float hi) {
    unsigned long long r;
    asm("mov.b64 %0, {%1,%2};" : "=l"(r) : "f"(lo), "f"(hi));
    return r;
}
__device__ __forceinline__ void unpack2(unsigned long long p, float& lo, float& hi) {
    asm("mov.b64 {%0,%1}, %2;" : "=f"(lo), "=f"(hi) : "l"(p));
}
__device__ __forceinline__ unsigned long long fma2(unsigned long long a,
                                                   unsigned long long b,
                                                   unsigned long long c) {
    unsigned long long d;
    asm("fma.rn.f32x2 %0, %1, %2, %3;" : "=l"(d) : "l"(a), "l"(b), "l"(c));
    return d;
}

// ---------------- kernel 0: init counters, sums, minbuf, pn-padding ----------
// grid 64 blocks x 256 threads
__global__ void k_zero() {
    int gid = blockIdx.x * 256 + threadIdx.x;      // 0..16383
    if (gid < 8) { ((int*)g_cnt)[gid] = 0; g_sum[gid] = 0.0f; }
    // minbuf: 8*16384 entries
    unsigned* mb = &g_minbuf[0][0];
    for (int i = gid; i < 8 * HW; i += 64 * 256) mb[i] = 0xFFFFFFFFu;
    // pn padding to +INF so out-of-range columns self-exclude in the min
    float* pn = &g_pn[0][0][0];
    for (int i = gid; i < 8 * HW; i += 64 * 256) pn[i] = CUDART_INF_F;
}

// ---------------- kernel 1: compaction ----------------
// grid (8 slices, 8 set*4+b), 256 threads; order within compacted array is free
__global__ void k_compact(const float* __restrict__ b1, const float* __restrict__ b2) {
    int bs = blockIdx.y;
    int set = bs >> 2, b = bs & 3;
    const float* src = (set == 0 ? b1 : b2) + b * HW;
    int begin = blockIdx.x * (HW / 8);             // 2048-element slice

    int lane = threadIdx.x & 31;
    for (int k = 0; k < (HW / 8) / 256; k++) {     // uniform trip count: ballot safe
        int i = begin + k * 256 + threadIdx.x;
        float v = src[i];
        float w = v - THR;
        bool act = (w > 0.0f);
        unsigned mask = __ballot_sync(0xffffffffu, act);
        int c = __popc(mask);
        int base = 0;
        if (lane == 0 && c) base = atomicAdd(&g_cnt[set][b], c);
        base = __shfl_sync(0xffffffffu, base, 0);
        if (act) {
            int pos = base + __popc(mask & ((1u << lane) - 1u));
            float y = (float)(i >> 7);
            float x = (float)(i & 127);
            float px = y * w, py = x * w;
            g_px[set][b][pos] = px;
            g_py[set][b][pos] = py;
            g_pn[set][b][pos] = fmaf(px, px, py * py);
        }
    }
}

// ---------------- kernel 2: pairwise min (GEMM-form) ----------------
// grid (8, 8, 8): x=row chunk (2048 rows), y=col chunk (2048 cols), z=dir*4+b
__global__ void __launch_bounds__(DBLK) k_dist() {
    int z = blockIdx.z;
    int dir = z >> 2, b = z & 3;
    int n1 = g_cnt[dir][b];          // rows come from set==dir
    int n2 = g_cnt[dir ^ 1][b];      // columns from the other set

    int rowBase = blockIdx.x * ROWCHUNK;
    int colBase = blockIdx.y * COLCHUNK;
    if (rowBase >= n1 || colBase >= n2) return;   // uniform per block

    __shared__ __align__(16) float sqx[TS];
    __shared__ __align__(16) float sqy[TS];
    __shared__ __align__(16) float sqn[TS];

    const float* qx = g_px[dir ^ 1][b];
    const float* qy = g_py[dir ^ 1][b];
    const float* qn = g_pn[dir ^ 1][b];

    int t = threadIdx.x;

    // vectorized unconditional tile load (pn padding = +INF excludes fake cols)
    {
        int j = t * 4;                              // 256*4 = 1024; two passes
        const float4* gx = (const float4*)(qx + colBase);
        const float4* gy = (const float4*)(qy + colBase);
        const float4* gn = (const float4*)(qn + colBase);
        ((float4*)sqx)[t]       = gx[t];
        ((float4*)sqy)[t]       = gy[t];
        ((float4*)sqn)[t]       = gn[t];
        ((float4*)sqx)[t + 256] = gx[t + 256];
        ((float4*)sqy)[t + 256] = gy[t + 256];
        ((float4*)sqn)[t + 256] = gn[t + 256];
        (void)j;
    }

    unsigned long long a2[RPT], b2[RPT];
    float mnL[RPT], mnH[RPT];
#pragma unroll
    for (int r = 0; r < RPT; r++) {
        int row = rowBase + t + r * DBLK;
        float px = 0.0f, py = 0.0f;
        if (row < n1) { px = g_px[dir][b][row]; py = g_py[dir][b][row]; }
        float a = -2.0f * px, bb = -2.0f * py;
        a2[r] = pack2(a, a);
        b2[r] = pack2(bb, bb);
        mnL[r] = CUDART_INF_F;
        mnH[r] = CUDART_INF_F;
    }

    __syncthreads();

#pragma unroll 4
    for (int j = 0; j < TS; j += 2) {
        unsigned long long qx2 = *(const unsigned long long*)&sqx[j];
        unsigned long long qy2 = *(const unsigned long long*)&sqy[j];
        unsigned long long qn2 = *(const unsigned long long*)&sqn[j];
#pragma unroll
        for (int r = 0; r < RPT; r++) {
            unsigned long long tp = fma2(b2[r], qy2, qn2);
            unsigned long long vp = fma2(a2[r], qx2, tp);
            float lo, hi;
            unpack2(vp, lo, hi);
            mnL[r] = fminf(mnL[r], lo);
            mnH[r] = fminf(mnH[r], hi);
        }
    }

#pragma unroll
    for (int r = 0; r < RPT; r++) {
        int row = rowBase + t + r * DBLK;
        if (row < n1) atomicMin(&g_minbuf[z][row], fp_ord(fminf(mnL[r], mnH[r])));
    }
}

// ---------------- kernel 3: per-direction partial sums ----------------
// grid (8 slices, 8 z), 256 threads
__global__ void k_final() {
    int z = blockIdx.y;
    int dir = z >> 2, b = z & 3;
    int n1 = g_cnt[dir][b];
    const float* pn = g_pn[dir][b];

    int begin = blockIdx.x * (HW / 8);
    int end   = min(begin + (HW / 8), n1);

    float s = 0.0f;
    for (int i = begin + threadIdx.x; i < end; i += 256) {
        float mv = fp_unord(g_minbuf[z][i]);
        float d2 = pn[i] + mv;
        s += sqrtf(fmaxf(d2, 1e-12f));
    }
    for (int o = 16; o; o >>= 1) s += __shfl_down_sync(0xffffffffu, s, o);
    __shared__ float ws[8];
    if ((threadIdx.x & 31) == 0) ws[threadIdx.x >> 5] = s;
    __syncthreads();
    if (threadIdx.x < 8) {
        float v = ws[threadIdx.x];
        for (int o = 4; o; o >>= 1) v += __shfl_down_sync(0xffu, v, o);
        if (threadIdx.x == 0) atomicAdd(&g_sum[z], v);
    }
}

// ---------------- kernel 4: combine + empty sentinel ----------------
__global__ void k_out(float* __restrict__ out) {
    int b = threadIdx.x;
    if (b < BATCH) {
        int n1 = g_cnt[0][b], n2 = g_cnt[1][b];
        float r = g_sum[b] / (float)max(n1, 1) + g_sum[4 + b] / (float)max(n2, 1);
        out[b] = (n1 > 0 && n2 > 0) ? r : 1.0e6f;
    }
}

// ---------------- launch ----------------
extern "C" void kernel_launch(void* const* d_in, const int* in_sizes, int n_in,
                              void* d_out, int out_size) {
    const float* b1 = (const float*)d_in[0];
    const float* b2 = (const float*)d_in[1];
    float* out = (float*)d_out;

    k_zero<<<64, 256>>>();
    {
        dim3 g(8, 8);
        k_compact<<<g, 256>>>(b1, b2);
    }
    {
        dim3 g(HW / ROWCHUNK, HW / COLCHUNK, 8);   // (8, 8, 8)
        k_dist<<<g, DBLK>>>();
    }
    {
        dim3 g(8, 8);
        k_final<<<g, 256>>>();
    }
    k_out<<<1, 32>>>(out);
}